// round 16
// baseline (speedup 1.0000x reference)
#include <cuda_runtime.h>
#include <cuda_fp16.h>
#include <math.h>
#include <stdint.h>

#define B_   4
#define T_   4096
#define C_   1024
#define H_   4096
#define E_   8
#define CAP_ 1024
#define G_   32
#define BK_  32
#define S_   40            // A smem row stride (elements)
#define SB_  264           // B smem row stride (elements), conflict-free
#define NT_  512           // 16 warps: 2m x 8n grid, warp tile 64x32

#define ABUF_ (128 * S_)                   // 5120 elems
#define BBUF_ (BK_ * SB_)                  // 8448 elems
#define STG_  (ABUF_ + BBUF_)              // 13568 elems per stage
#define NSTG_ 3
#define SMEM_BYTES_ (NSTG_ * STG_ * 2)     // 81408 B

// ======== scratch: ALL 32-bit-typed symbols; exactly 5 kernels ========
__device__ float    g_probs[B_ * E_ * T_];
__device__ float    g_topp[G_ * CAP_];
__device__ int      g_topi[G_ * CAP_];
__device__ uint32_t g_xg [(size_t)G_ * CAP_ * C_ / 2];  //  32 MB gathered tokens fp16
__device__ uint32_t g_w1h[(size_t)E_ * C_ * H_ / 2];    //  64 MB w1 fp16
__device__ uint32_t g_w2h[(size_t)E_ * H_ * C_ / 2];    //  64 MB w2 fp16
__device__ uint32_t g_h16[(size_t)G_ * CAP_ * H_ / 2];  // 256 MB hidden acts fp16

// ======== helpers ========
__device__ __forceinline__ uint32_t smem_u32(const void* p) {
    uint32_t a;
    asm("{ .reg .u64 t; cvta.to.shared.u64 t, %1; cvt.u32.u64 %0, t; }" : "=r"(a) : "l"(p));
    return a;
}
__device__ __forceinline__ float gelu_f(float v) {
    return 0.5f * v * (1.0f + erff(v * 0.70710678118654752f));
}
__device__ __forceinline__ void mma16816h(float* d, const uint32_t* a, const uint32_t* b) {
    asm volatile("mma.sync.aligned.m16n8k16.row.col.f32.f16.f16.f32 "
        "{%0,%1,%2,%3}, {%4,%5,%6,%7}, {%8,%9}, {%0,%1,%2,%3};"
        : "+f"(d[0]), "+f"(d[1]), "+f"(d[2]), "+f"(d[3])
        : "r"(a[0]), "r"(a[1]), "r"(a[2]), "r"(a[3]), "r"(b[0]), "r"(b[1]));
}
#define LDSM_X4(r, addr) \
    asm volatile("ldmatrix.sync.aligned.m8n8.x4.shared.b16 {%0,%1,%2,%3}, [%4];" \
        : "=r"((r)[0]), "=r"((r)[1]), "=r"((r)[2]), "=r"((r)[3]) : "r"(addr))
#define LDSM_X4_T(r, addr) \
    asm volatile("ldmatrix.sync.aligned.m8n8.x4.trans.shared.b16 {%0,%1,%2,%3}, [%4];" \
        : "=r"((r)[0]), "=r"((r)[1]), "=r"((r)[2]), "=r"((r)[3]) : "r"(addr))
#define CPA16(dst, src) \
    asm volatile("cp.async.cg.shared.global [%0], [%1], 16;" \
        :: "r"(dst), "l"(__cvta_generic_to_global(src)) : "memory")
#define CPA_COMMIT() asm volatile("cp.async.commit_group;" ::: "memory")
#define CPA_WAIT1()  asm volatile("cp.async.wait_group 1;" ::: "memory")
#define CPA_WAIT0()  asm volatile("cp.async.wait_group 0;" ::: "memory")

// ======== kernel 1: gate + softmax + zero-init out (proven) ========
__global__ __launch_bounds__(256) void gate_kernel(const float* __restrict__ x,
                                                   const float* __restrict__ gw,
                                                   float4* __restrict__ out4) {
    {
        const int base = blockIdx.x * 256 + threadIdx.x;
        const float4 z = make_float4(0.f, 0.f, 0.f, 0.f);
#pragma unroll
        for (int q = 0; q < 8; q++) out4[base + q * 524288] = z;
    }
    __shared__ float sgw[E_][C_];
    for (int i = threadIdx.x; i < C_ * E_; i += 256) {
        int c = i >> 3, e = i & 7;
        sgw[e][c] = gw[i];
    }
    __syncthreads();
    const int warp = threadIdx.x >> 5, lane = threadIdx.x & 31;
    const int token = blockIdx.x * 8 + warp;
    const float* xrow = x + (size_t)token * C_;
    float acc[E_];
#pragma unroll
    for (int e = 0; e < E_; e++) acc[e] = 0.f;
    for (int c = lane; c < C_; c += 32) {
        float xv = xrow[c];
#pragma unroll
        for (int e = 0; e < E_; e++) acc[e] = fmaf(xv, sgw[e][c], acc[e]);
    }
#pragma unroll
    for (int off = 16; off > 0; off >>= 1)
#pragma unroll
        for (int e = 0; e < E_; e++) acc[e] += __shfl_xor_sync(0xffffffffu, acc[e], off);
    if (lane == 0) {
        float mx = acc[0];
#pragma unroll
        for (int e = 1; e < E_; e++) mx = fmaxf(mx, acc[e]);
        float s = 0.f, ex[E_];
#pragma unroll
        for (int e = 0; e < E_; e++) { ex[e] = expf(acc[e] - mx); s += ex[e]; }
        float inv = 1.0f / s;
        const int b = token >> 12, t = token & (T_ - 1);
#pragma unroll
        for (int e = 0; e < E_; e++)
            g_probs[((size_t)(b * E_ + e)) * T_ + t] = ex[e] * inv;
    }
}

// ======== kernel 2: top-k bitonic (proven) ========
__global__ __launch_bounds__(1024) void topk_kernel() {
    __shared__ unsigned long long keys[T_];
    const int g = blockIdx.x;
    const float* p = g_probs + (size_t)g * T_;
    for (int i = threadIdx.x; i < T_; i += 1024) {
        unsigned pb = __float_as_uint(p[i]);
        keys[i] = ((unsigned long long)pb << 32) | (unsigned)(0xFFFFFFFFu - (unsigned)i);
    }
    __syncthreads();
    for (int k = 2; k <= T_; k <<= 1)
        for (int j = k >> 1; j > 0; j >>= 1) {
            for (int i = threadIdx.x; i < T_; i += 1024) {
                int ixj = i ^ j;
                if (ixj > i) {
                    unsigned long long a = keys[i], bb = keys[ixj];
                    bool dsc = ((i & k) == 0);
                    if (dsc ? (a < bb) : (a > bb)) { keys[i] = bb; keys[ixj] = a; }
                }
            }
            __syncthreads();
        }
    for (int i = threadIdx.x; i < CAP_; i += 1024) {
        unsigned long long kv = keys[i];
        g_topp[(size_t)g * CAP_ + i] = __uint_as_float((unsigned)(kv >> 32));
        g_topi[(size_t)g * CAP_ + i] = (int)(0xFFFFFFFFu - (unsigned)kv);
    }
}

// ======== kernel 3: prep = w1 | w2 | gather (proven R15) ========
__global__ __launch_bounds__(256) void prep_kernel(const float* __restrict__ x,
                                                   const float* __restrict__ w1,
                                                   const float* __restrict__ w2) {
    const int WB = (E_ * C_ * H_) / (256 * 8);      // 16384
    const int tid = threadIdx.x;
    if (blockIdx.x < 2 * WB) {
        const bool first = (blockIdx.x < WB);
        const float* in = first ? w1 : w2;
        uint32_t* out = first ? g_w1h : g_w2h;
        const int bid = first ? blockIdx.x : (blockIdx.x - WB);
        const size_t i = ((size_t)bid * 256 + tid) * 8;
        float4 v0 = *(const float4*)(in + i);
        float4 v1 = *(const float4*)(in + i + 4);
        __align__(16) __half h[8];
        h[0] = __float2half(v0.x); h[1] = __float2half(v0.y);
        h[2] = __float2half(v0.z); h[3] = __float2half(v0.w);
        h[4] = __float2half(v1.x); h[5] = __float2half(v1.y);
        h[6] = __float2half(v1.z); h[7] = __float2half(v1.w);
        *(uint4*)(out + i / 2) = *(uint4*)h;
    } else {
        const int gi = (blockIdx.x - 2 * WB) * 2 + (tid >> 7);
        const int g = gi >> 10, b = g >> 3;
        const int tok = g_topi[gi];
        const int t = tid & 127;
        const float4* src = (const float4*)(x + ((size_t)(b * T_ + tok)) * C_) + 2 * t;
        float4 v0 = src[0], v1 = src[1];
        __align__(16) __half h[8];
        h[0] = __float2half(v0.x); h[1] = __float2half(v0.y);
        h[2] = __float2half(v0.z); h[3] = __float2half(v0.w);
        h[4] = __float2half(v1.x); h[5] = __float2half(v1.y);
        h[6] = __float2half(v1.z); h[7] = __float2half(v1.w);
        *(uint4*)(g_xg + (size_t)gi * (C_ / 2) + t * 4) = *(uint4*)h;
    }
}

// ======== MMA tile core: 512 thr, 3-stage cp.async, warp tile 64x32 ========
// A [128][S_]: thread -> row tid>>2, chunk (tid&3)*8   (512 chunks)
// B [32][SB_]: thread -> k-row tid>>4, 16 n-elems at (tid&15)*16 (2 chunks)
__device__ __forceinline__ void mma_tile(
    const __half* __restrict__ gA, int kstrideA,
    const __half* __restrict__ gB, int kstrideB,
    int nkb, __half* dsm, float acc[4][4][4])
{
    const int tid  = threadIdx.x;
    const int warp = tid >> 5, lane = tid & 31;
    const int m_off = (warp >> 3) * 64;
    const int n_off = (warp & 7) * 32;

    const int rA = tid >> 2, kcA = (tid & 3) * 8;
    const int krB = tid >> 4, ncB = (tid & 15) * 16;
    const __half* srcA = gA + (size_t)rA * kstrideA + kcA;
    const __half* srcB = gB + (size_t)krB * kstrideB + ncB;
    const uint32_t ub = smem_u32(dsm);
    const uint32_t dA = (uint32_t)((rA * S_ + kcA) * 2);
    const uint32_t dB = (uint32_t)((krB * SB_ + ncB) * 2 + ABUF_ * 2);

    const uint32_t aoff = (uint32_t)(((m_off + (lane & 15)) * S_ + ((lane & 16) ? 8 : 0)) * 2);
    const uint32_t boff = (uint32_t)(((lane & 15) * SB_ + n_off + ((lane & 16) ? 8 : 0)) * 2 + ABUF_ * 2);

#define ISSUE_STAGE(st, kb) do {                                                      \
    const uint32_t _sb = ub + (uint32_t)(st) * (STG_ * 2);                            \
    CPA16(_sb + dA, srcA + (size_t)(kb) * BK_);                                       \
    const __half* _pb = srcB + (size_t)(kb) * BK_ * kstrideB;                         \
    CPA16(_sb + dB,       _pb);                                                       \
    CPA16(_sb + dB + 16u, _pb + 8);                                                   \
    CPA_COMMIT();                                                                     \
} while (0)

    ISSUE_STAGE(0, 0);
    ISSUE_STAGE(1, 1);

    for (int kb = 0; kb < nkb; kb++) {
        if (kb + 1 < nkb) CPA_WAIT1(); else CPA_WAIT0();
        __syncthreads();
        if (kb + 2 < nkb) ISSUE_STAGE((kb + 2) % NSTG_, kb + 2);

        const uint32_t sbase = ub + (uint32_t)(kb % NSTG_) * (STG_ * 2);
#pragma unroll
        for (int ks = 0; ks < BK_; ks += 16) {
            uint32_t ah[4][4];
#pragma unroll
            for (int mt = 0; mt < 4; mt++)
                LDSM_X4(ah[mt], sbase + aoff + (uint32_t)((mt * 16 * S_ + ks) * 2));
#pragma unroll
            for (int pair = 0; pair < 2; pair++) {
                uint32_t bh[4];
                LDSM_X4_T(bh, sbase + boff + (uint32_t)((ks * SB_ + pair * 16) * 2));
#pragma unroll
                for (int sub = 0; sub < 2; sub++) {
                    const int nt = pair * 2 + sub;
#pragma unroll
                    for (int mt = 0; mt < 4; mt++)
                        mma16816h(acc[mt][nt], ah[mt], bh + 2 * sub);
                }
            }
        }
    }
#undef ISSUE_STAGE
}

// ======== kernel 4: GEMM1 = gelu(xg @ w1h[e]) -> g_h16 ========
__global__ __launch_bounds__(NT_) void gemm1_mma() {
    extern __shared__ __align__(16) __half dsm[];
    const int tid = threadIdx.x;
    const int g = blockIdx.z, e = g & 7;
    const int m0 = blockIdx.y << 7, n0 = blockIdx.x << 8;

    float acc[4][4][4];
#pragma unroll
    for (int mt = 0; mt < 4; mt++)
#pragma unroll
        for (int nt = 0; nt < 4; nt++)
#pragma unroll
            for (int i = 0; i < 4; i++) acc[mt][nt][i] = 0.f;

    mma_tile((const __half*)g_xg + ((size_t)g * CAP_ + m0) * C_, C_,
             (const __half*)g_w1h + (size_t)e * C_ * H_ + n0, H_,
             C_ / BK_, dsm, acc);

    const int warp = tid >> 5, lane = tid & 31;
    const int gq = lane >> 2, tq = lane & 3;
    const int m_off = (warp >> 3) * 64, n_off = (warp & 7) * 32;
#pragma unroll
    for (int mt = 0; mt < 4; mt++) {
        const int r0l = m_off + mt * 16 + gq;
#pragma unroll
        for (int nt = 0; nt < 4; nt++) {
            const int col = n0 + n_off + nt * 8 + tq * 2;
#pragma unroll
            for (int hrow = 0; hrow < 2; hrow++) {
                const int rl = r0l + hrow * 8;
                __half2 hv = __halves2half2(
                    __float2half(gelu_f(acc[mt][nt][2 * hrow + 0])),
                    __float2half(gelu_f(acc[mt][nt][2 * hrow + 1])));
                g_h16[((size_t)g * CAP_ + m0 + rl) * (H_ / 2) + (col >> 1)]
                    = *(uint32_t*)&hv;
            }
        }
    }
}

// ======== kernel 5: GEMM2 = scatter(p * (g_h16 @ w2h[e])) ========
__global__ __launch_bounds__(NT_) void gemm2_mma(float* __restrict__ out) {
    extern __shared__ __align__(16) __half dsm[];
    __shared__ int   s_tok[128];
    __shared__ float s_p[128];

    const int tid = threadIdx.x;
    const int g = blockIdx.z, b = g >> 3, e = g & 7;
    const int m0 = blockIdx.y << 7, n0 = blockIdx.x << 8;
    if (tid < 128) {
        s_tok[tid] = g_topi[(size_t)g * CAP_ + m0 + tid];
        s_p[tid]   = g_topp[(size_t)g * CAP_ + m0 + tid];
    }
    __syncthreads();

    float acc[4][4][4];
#pragma unroll
    for (int mt = 0; mt < 4; mt++)
#pragma unroll
        for (int nt = 0; nt < 4; nt++)
#pragma unroll
            for (int i = 0; i < 4; i++) acc[mt][nt][i] = 0.f;

    mma_tile((const __half*)g_h16 + ((size_t)g * CAP_ + m0) * H_, H_,
             (const __half*)g_w2h + (size_t)e * H_ * C_ + n0, C_,
             H_ / BK_, dsm, acc);

    const int warp = tid >> 5, lane = tid & 31;
    const int gq = lane >> 2, tq = lane & 3;
    const int m_off = (warp >> 3) * 64, n_off = (warp & 7) * 32;
#pragma unroll
    for (int mt = 0; mt < 4; mt++) {
        const int r0l = m_off + mt * 16 + gq;
#pragma unroll
        for (int nt = 0; nt < 4; nt++) {
            const int col = n0 + n_off + nt * 8 + tq * 2;
#pragma unroll
            for (int hrow = 0; hrow < 2; hrow++) {
                const int rl = r0l + hrow * 8;
                const int tok = s_tok[rl];
                const float p = s_p[rl];
                float* orow = out + ((size_t)b * T_ + tok) * C_ + col;
                atomicAdd(orow,     acc[mt][nt][2 * hrow + 0] * p);
                atomicAdd(orow + 1, acc[mt][nt][2 * hrow + 1] * p);
            }
        }
    }
}

// ======== launch (exactly 5 kernels) ========
extern "C" void kernel_launch(void* const* d_in, const int* in_sizes, int n_in,
                              void* d_out, int out_size) {
    const float* x  = (const float*)d_in[0];
    const float* gw = (const float*)d_in[1];
    const float* w1 = (const float*)d_in[2];
    const float* w2 = (const float*)d_in[3];
    float* out = (float*)d_out;

    cudaFuncSetAttribute(gemm1_mma, cudaFuncAttributeMaxDynamicSharedMemorySize, SMEM_BYTES_);
    cudaFuncSetAttribute(gemm2_mma, cudaFuncAttributeMaxDynamicSharedMemorySize, SMEM_BYTES_);

    gate_kernel<<<(B_ * T_) / 8, 256>>>(x, gw, (float4*)out);
    topk_kernel<<<G_, 1024>>>();

    const int WB = (E_ * C_ * H_) / (256 * 8);          // 16384
    prep_kernel<<<2 * WB + (G_ * CAP_) / 2, 256>>>(x, w1, w2);

    gemm1_mma<<<dim3(H_ / 256, CAP_ / 128, G_), NT_, SMEM_BYTES_>>>();
    gemm2_mma<<<dim3(C_ / 256, CAP_ / 128, G_), NT_, SMEM_BYTES_>>>(out);
}

// round 17
// speedup vs baseline: 1.1884x; 1.1884x over previous
#include <cuda_runtime.h>
#include <cuda_fp16.h>
#include <math.h>
#include <stdint.h>

#define B_   4
#define T_   4096
#define C_   1024
#define H_   4096
#define E_   8
#define CAP_ 1024
#define G_   32
#define BK_  64            // K-block (doubled vs R15)
#define S_   72            // A smem row stride (elems): 144B rows, LDSM conflict-free
#define SB_  264           // B smem row stride (elems), conflict-free

#define ABUF_ (128 * S_)                   // 9216 elems
#define BBUF_ (BK_ * SB_)                  // 16896 elems
#define STG_  (ABUF_ + BBUF_)              // 26112 elems per stage
#define SMEM_BYTES_ (2 * STG_ * 2)         // 104448 B

// ======== scratch: ALL 32-bit-typed symbols; exactly 5 kernels (hard constraints) ========
__device__ float    g_probs[B_ * E_ * T_];
__device__ float    g_topp[G_ * CAP_];
__device__ int      g_topi[G_ * CAP_];
__device__ uint32_t g_xg [(size_t)G_ * CAP_ * C_ / 2];  //  32 MB gathered tokens fp16
__device__ uint32_t g_w1h[(size_t)E_ * C_ * H_ / 2];    //  64 MB w1 fp16
__device__ uint32_t g_w2h[(size_t)E_ * H_ * C_ / 2];    //  64 MB w2 fp16
__device__ uint32_t g_h16[(size_t)G_ * CAP_ * H_ / 2];  // 256 MB hidden acts fp16

// ======== helpers ========
__device__ __forceinline__ uint32_t smem_u32(const void* p) {
    uint32_t a;
    asm("{ .reg .u64 t; cvta.to.shared.u64 t, %1; cvt.u32.u64 %0, t; }" : "=r"(a) : "l"(p));
    return a;
}
__device__ __forceinline__ float gelu_f(float v) {
    return 0.5f * v * (1.0f + erff(v * 0.70710678118654752f));
}
__device__ __forceinline__ void mma16816h(float* d, const uint32_t* a, const uint32_t* b) {
    asm volatile("mma.sync.aligned.m16n8k16.row.col.f32.f16.f16.f32 "
        "{%0,%1,%2,%3}, {%4,%5,%6,%7}, {%8,%9}, {%0,%1,%2,%3};"
        : "+f"(d[0]), "+f"(d[1]), "+f"(d[2]), "+f"(d[3])
        : "r"(a[0]), "r"(a[1]), "r"(a[2]), "r"(a[3]), "r"(b[0]), "r"(b[1]));
}
#define LDSM_X4(r, addr) \
    asm volatile("ldmatrix.sync.aligned.m8n8.x4.shared.b16 {%0,%1,%2,%3}, [%4];" \
        : "=r"((r)[0]), "=r"((r)[1]), "=r"((r)[2]), "=r"((r)[3]) : "r"(addr))
#define LDSM_X4_T(r, addr) \
    asm volatile("ldmatrix.sync.aligned.m8n8.x4.trans.shared.b16 {%0,%1,%2,%3}, [%4];" \
        : "=r"((r)[0]), "=r"((r)[1]), "=r"((r)[2]), "=r"((r)[3]) : "r"(addr))
#define CPA16(dst, src) \
    asm volatile("cp.async.cg.shared.global [%0], [%1], 16;" \
        :: "r"(dst), "l"(__cvta_generic_to_global(src)) : "memory")
#define CPA_COMMIT() asm volatile("cp.async.commit_group;" ::: "memory")
#define CPA_WAIT0()  asm volatile("cp.async.wait_group 0;" ::: "memory")

// ======== kernel 1: gate + softmax + zero-init out (proven) ========
__global__ __launch_bounds__(256) void gate_kernel(const float* __restrict__ x,
                                                   const float* __restrict__ gw,
                                                   float4* __restrict__ out4) {
    {
        const int base = blockIdx.x * 256 + threadIdx.x;
        const float4 z = make_float4(0.f, 0.f, 0.f, 0.f);
#pragma unroll
        for (int q = 0; q < 8; q++) out4[base + q * 524288] = z;
    }
    __shared__ float sgw[E_][C_];
    for (int i = threadIdx.x; i < C_ * E_; i += 256) {
        int c = i >> 3, e = i & 7;
        sgw[e][c] = gw[i];
    }
    __syncthreads();
    const int warp = threadIdx.x >> 5, lane = threadIdx.x & 31;
    const int token = blockIdx.x * 8 + warp;
    const float* xrow = x + (size_t)token * C_;
    float acc[E_];
#pragma unroll
    for (int e = 0; e < E_; e++) acc[e] = 0.f;
    for (int c = lane; c < C_; c += 32) {
        float xv = xrow[c];
#pragma unroll
        for (int e = 0; e < E_; e++) acc[e] = fmaf(xv, sgw[e][c], acc[e]);
    }
#pragma unroll
    for (int off = 16; off > 0; off >>= 1)
#pragma unroll
        for (int e = 0; e < E_; e++) acc[e] += __shfl_xor_sync(0xffffffffu, acc[e], off);
    if (lane == 0) {
        float mx = acc[0];
#pragma unroll
        for (int e = 1; e < E_; e++) mx = fmaxf(mx, acc[e]);
        float s = 0.f, ex[E_];
#pragma unroll
        for (int e = 0; e < E_; e++) { ex[e] = expf(acc[e] - mx); s += ex[e]; }
        float inv = 1.0f / s;
        const int b = token >> 12, t = token & (T_ - 1);
#pragma unroll
        for (int e = 0; e < E_; e++)
            g_probs[((size_t)(b * E_ + e)) * T_ + t] = ex[e] * inv;
    }
}

// ======== kernel 2: top-k bitonic (proven) ========
__global__ __launch_bounds__(1024) void topk_kernel() {
    __shared__ unsigned long long keys[T_];
    const int g = blockIdx.x;
    const float* p = g_probs + (size_t)g * T_;
    for (int i = threadIdx.x; i < T_; i += 1024) {
        unsigned pb = __float_as_uint(p[i]);
        keys[i] = ((unsigned long long)pb << 32) | (unsigned)(0xFFFFFFFFu - (unsigned)i);
    }
    __syncthreads();
    for (int k = 2; k <= T_; k <<= 1)
        for (int j = k >> 1; j > 0; j >>= 1) {
            for (int i = threadIdx.x; i < T_; i += 1024) {
                int ixj = i ^ j;
                if (ixj > i) {
                    unsigned long long a = keys[i], bb = keys[ixj];
                    bool dsc = ((i & k) == 0);
                    if (dsc ? (a < bb) : (a > bb)) { keys[i] = bb; keys[ixj] = a; }
                }
            }
            __syncthreads();
        }
    for (int i = threadIdx.x; i < CAP_; i += 1024) {
        unsigned long long kv = keys[i];
        g_topp[(size_t)g * CAP_ + i] = __uint_as_float((unsigned)(kv >> 32));
        g_topi[(size_t)g * CAP_ + i] = (int)(0xFFFFFFFFu - (unsigned)kv);
    }
}

// ======== kernel 3: prep = w1 | w2 | gather (proven) ========
__global__ __launch_bounds__(256) void prep_kernel(const float* __restrict__ x,
                                                   const float* __restrict__ w1,
                                                   const float* __restrict__ w2) {
    const int WB = (E_ * C_ * H_) / (256 * 8);      // 16384
    const int tid = threadIdx.x;
    if (blockIdx.x < 2 * WB) {
        const bool first = (blockIdx.x < WB);
        const float* in = first ? w1 : w2;
        uint32_t* out = first ? g_w1h : g_w2h;
        const int bid = first ? blockIdx.x : (blockIdx.x - WB);
        const size_t i = ((size_t)bid * 256 + tid) * 8;
        float4 v0 = *(const float4*)(in + i);
        float4 v1 = *(const float4*)(in + i + 4);
        __align__(16) __half h[8];
        h[0] = __float2half(v0.x); h[1] = __float2half(v0.y);
        h[2] = __float2half(v0.z); h[3] = __float2half(v0.w);
        h[4] = __float2half(v1.x); h[5] = __float2half(v1.y);
        h[6] = __float2half(v1.z); h[7] = __float2half(v1.w);
        *(uint4*)(out + i / 2) = *(uint4*)h;
    } else {
        const int gi = (blockIdx.x - 2 * WB) * 2 + (tid >> 7);
        const int g = gi >> 10, b = g >> 3;
        const int tok = g_topi[gi];
        const int t = tid & 127;
        const float4* src = (const float4*)(x + ((size_t)(b * T_ + tok)) * C_) + 2 * t;
        float4 v0 = src[0], v1 = src[1];
        __align__(16) __half h[8];
        h[0] = __float2half(v0.x); h[1] = __float2half(v0.y);
        h[2] = __float2half(v0.z); h[3] = __float2half(v0.w);
        h[4] = __float2half(v1.x); h[5] = __float2half(v1.y);
        h[6] = __float2half(v1.z); h[7] = __float2half(v1.w);
        *(uint4*)(g_xg + (size_t)gi * (C_ / 2) + t * 4) = *(uint4*)h;
    }
}

// ======== MMA tile core: 256 thr, warp tile 64x64, BK=64, 2-stage cp.async ========
// A [128][S_]: thread -> row tid>>1, 4 chunks at (tid&1)*32 + 8j
// B [64][SB_]: thread -> k-row tid>>2, 8 chunks at (tid&3)*64 + 8j
__device__ __forceinline__ void mma_tile(
    const __half* __restrict__ gA, int kstrideA,
    const __half* __restrict__ gB, int kstrideB,
    int nkb, __half* dsm, float acc[4][8][4])
{
    const int tid  = threadIdx.x;
    const int warp = tid >> 5, lane = tid & 31;
    const int m_off = (warp >> 2) * 64;
    const int n_off = (warp & 3) * 64;

    const int rA  = tid >> 1, kcA = (tid & 1) * 32;
    const int krB = tid >> 2, ncB = (tid & 3) * 64;
    const __half* srcA = gA + (size_t)rA * kstrideA + kcA;
    const __half* srcB = gB + (size_t)krB * kstrideB + ncB;
    const uint32_t ub = smem_u32(dsm);
    const uint32_t dA = (uint32_t)((rA * S_ + kcA) * 2);
    const uint32_t dB = (uint32_t)((krB * SB_ + ncB) * 2 + ABUF_ * 2);

    const uint32_t aoff = (uint32_t)(((m_off + (lane & 15)) * S_ + ((lane & 16) ? 8 : 0)) * 2);
    const uint32_t boff = (uint32_t)(((lane & 15) * SB_ + n_off + ((lane & 16) ? 8 : 0)) * 2 + ABUF_ * 2);

#define ISSUE_STAGE(st, kb) do {                                                      \
    const uint32_t _sb = ub + (uint32_t)(st) * (STG_ * 2);                            \
    const __half* _pa = srcA + (size_t)(kb) * BK_;                                    \
    CPA16(_sb + dA,       _pa);      CPA16(_sb + dA + 16u, _pa + 8);                  \
    CPA16(_sb + dA + 32u, _pa + 16); CPA16(_sb + dA + 48u, _pa + 24);                 \
    const __half* _pb = srcB + (size_t)(kb) * BK_ * kstrideB;                         \
    CPA16(_sb + dB,        _pb);      CPA16(_sb + dB + 16u,  _pb + 8);                \
    CPA16(_sb + dB + 32u,  _pb + 16); CPA16(_sb + dB + 48u,  _pb + 24);               \
    CPA16(_sb + dB + 64u,  _pb + 32); CPA16(_sb + dB + 80u,  _pb + 40);               \
    CPA16(_sb + dB + 96u,  _pb + 48); CPA16(_sb + dB + 112u, _pb + 56);               \
    CPA_COMMIT();                                                                     \
} while (0)

    ISSUE_STAGE(0, 0);

    for (int kb = 0; kb < nkb; kb++) {
        const int s = kb & 1;
        CPA_WAIT0();
        __syncthreads();
        if (kb + 1 < nkb) ISSUE_STAGE(s ^ 1, kb + 1);

        const uint32_t sbase = ub + (uint32_t)s * (STG_ * 2);
#pragma unroll
        for (int ks = 0; ks < BK_; ks += 16) {
            uint32_t ah[4][4];
#pragma unroll
            for (int mt = 0; mt < 4; mt++)
                LDSM_X4(ah[mt], sbase + aoff + (uint32_t)((mt * 16 * S_ + ks) * 2));
#pragma unroll
            for (int pair = 0; pair < 4; pair++) {
                uint32_t bh[4];
                LDSM_X4_T(bh, sbase + boff + (uint32_t)((ks * SB_ + pair * 16) * 2));
#pragma unroll
                for (int sub = 0; sub < 2; sub++) {
                    const int nt = pair * 2 + sub;
#pragma unroll
                    for (int mt = 0; mt < 4; mt++)
                        mma16816h(acc[mt][nt], ah[mt], bh + 2 * sub);
                }
            }
        }
    }
#undef ISSUE_STAGE
}

// ======== kernel 4: GEMM1 = gelu(xg @ w1h[e]) -> g_h16, CTA 128x256 ========
__global__ __launch_bounds__(256) void gemm1_mma() {
    extern __shared__ __align__(16) __half dsm[];
    const int tid = threadIdx.x;
    const int g = blockIdx.z, e = g & 7;
    const int m0 = blockIdx.y << 7, n0 = blockIdx.x << 8;

    float acc[4][8][4];
#pragma unroll
    for (int mt = 0; mt < 4; mt++)
#pragma unroll
        for (int nt = 0; nt < 8; nt++)
#pragma unroll
            for (int i = 0; i < 4; i++) acc[mt][nt][i] = 0.f;

    mma_tile((const __half*)g_xg + ((size_t)g * CAP_ + m0) * C_, C_,
             (const __half*)g_w1h + (size_t)e * C_ * H_ + n0, H_,
             C_ / BK_, dsm, acc);

    const int warp = tid >> 5, lane = tid & 31;
    const int gq = lane >> 2, tq = lane & 3;
    const int m_off = (warp >> 2) * 64, n_off = (warp & 3) * 64;
#pragma unroll
    for (int mt = 0; mt < 4; mt++) {
        const int r0l = m_off + mt * 16 + gq;
#pragma unroll
        for (int nt = 0; nt < 8; nt++) {
            const int col = n0 + n_off + nt * 8 + tq * 2;
#pragma unroll
            for (int hrow = 0; hrow < 2; hrow++) {
                const int rl = r0l + hrow * 8;
                __half2 hv = __halves2half2(
                    __float2half(gelu_f(acc[mt][nt][2 * hrow + 0])),
                    __float2half(gelu_f(acc[mt][nt][2 * hrow + 1])));
                g_h16[((size_t)g * CAP_ + m0 + rl) * (H_ / 2) + (col >> 1)]
                    = *(uint32_t*)&hv;
            }
        }
    }
}

// ======== kernel 5: GEMM2 = scatter(p * (g_h16 @ w2h[e])), CTA 128x256 ========
__global__ __launch_bounds__(256) void gemm2_mma(float* __restrict__ out) {
    extern __shared__ __align__(16) __half dsm[];
    __shared__ int   s_tok[128];
    __shared__ float s_p[128];

    const int tid = threadIdx.x;
    const int g = blockIdx.z, b = g >> 3, e = g & 7;
    const int m0 = blockIdx.y << 7, n0 = blockIdx.x << 8;
    if (tid < 128) {
        s_tok[tid] = g_topi[(size_t)g * CAP_ + m0 + tid];
        s_p[tid]   = g_topp[(size_t)g * CAP_ + m0 + tid];
    }
    __syncthreads();

    float acc[4][8][4];
#pragma unroll
    for (int mt = 0; mt < 4; mt++)
#pragma unroll
        for (int nt = 0; nt < 8; nt++)
#pragma unroll
            for (int i = 0; i < 4; i++) acc[mt][nt][i] = 0.f;

    mma_tile((const __half*)g_h16 + ((size_t)g * CAP_ + m0) * H_, H_,
             (const __half*)g_w2h + (size_t)e * H_ * C_ + n0, C_,
             H_ / BK_, dsm, acc);

    const int warp = tid >> 5, lane = tid & 31;
    const int gq = lane >> 2, tq = lane & 3;
    const int m_off = (warp >> 2) * 64, n_off = (warp & 3) * 64;
#pragma unroll
    for (int mt = 0; mt < 4; mt++) {
        const int r0l = m_off + mt * 16 + gq;
#pragma unroll
        for (int nt = 0; nt < 8; nt++) {
            const int col = n0 + n_off + nt * 8 + tq * 2;
#pragma unroll
            for (int hrow = 0; hrow < 2; hrow++) {
                const int rl = r0l + hrow * 8;
                const int tok = s_tok[rl];
                const float p = s_p[rl];
                float* orow = out + ((size_t)b * T_ + tok) * C_ + col;
                atomicAdd(orow,     acc[mt][nt][2 * hrow + 0] * p);
                atomicAdd(orow + 1, acc[mt][nt][2 * hrow + 1] * p);
            }
        }
    }
}

// ======== launch (exactly 5 kernels) ========
extern "C" void kernel_launch(void* const* d_in, const int* in_sizes, int n_in,
                              void* d_out, int out_size) {
    const float* x  = (const float*)d_in[0];
    const float* gw = (const float*)d_in[1];
    const float* w1 = (const float*)d_in[2];
    const float* w2 = (const float*)d_in[3];
    float* out = (float*)d_out;

    cudaFuncSetAttribute(gemm1_mma, cudaFuncAttributeMaxDynamicSharedMemorySize, SMEM_BYTES_);
    cudaFuncSetAttribute(gemm2_mma, cudaFuncAttributeMaxDynamicSharedMemorySize, SMEM_BYTES_);

    gate_kernel<<<(B_ * T_) / 8, 256>>>(x, gw, (float4*)out);
    topk_kernel<<<G_, 1024>>>();

    const int WB = (E_ * C_ * H_) / (256 * 8);          // 16384
    prep_kernel<<<2 * WB + (G_ * CAP_) / 2, 256>>>(x, w1, w2);

    gemm1_mma<<<dim3(H_ / 256, CAP_ / 128, G_), 256, SMEM_BYTES_>>>();
    gemm2_mma<<<dim3(C_ / 256, CAP_ / 128, G_), 256, SMEM_BYTES_>>>(out);
}